// round 12
// baseline (speedup 1.0000x reference)
#include <cuda_runtime.h>
#include <cuda_bf16.h>

// out[b,f] = input[b,f] * weight[f] + bias[nb_distrib, f]
// B=16384, F=4096, fp32. DRAM-bound stream (R8/R11: DRAM 80.8%, 6.4 TB/s).
// This round: persistent single-wave grid (152 SMs x 8 CTAs = 1216 blocks,
// grid-stride over 16384 row-strips) to eliminate ~13 wave transitions whose
// DRAM-queue drain/ramp is the best remaining explanation for the 19% of
// idle DRAM cycles. Streaming .cs policy kept (neutral, protective).

static constexpr int F_DIM      = 4096;
static constexpr int F_VEC      = F_DIM / 4;            // 1024 float4 per row
static constexpr unsigned N_STRIPS = 16384u;            // one strip == one row
static constexpr int THREADS    = 256;
static constexpr int BLOCKS     = 152 * 8;              // one full wave on GB300

__global__ __launch_bounds__(THREADS)
void sharelinear_kernel(const float4* __restrict__ in,
                        const float4* __restrict__ weight,
                        const float4* __restrict__ bias,
                        const int*    __restrict__ nb_distrib,
                        float4*       __restrict__ out)
{
    const int nb = *nb_distrib;
    const float4* __restrict__ brow = bias + (unsigned)nb * F_VEC;

    const unsigned tid = threadIdx.x;
    const unsigned f0 = tid + 0u * 256u;   // strips are row-aligned -> f fixed
    const unsigned f1 = tid + 1u * 256u;
    const unsigned f2 = tid + 2u * 256u;
    const unsigned f3 = tid + 3u * 256u;

    // Weight/bias loads are loop-invariant: hoist once per CTA. L2-resident.
    const float4 w0 = __ldg(weight + f0), b0 = __ldg(brow + f0);
    const float4 w1 = __ldg(weight + f1), b1 = __ldg(brow + f1);
    const float4 w2 = __ldg(weight + f2), b2 = __ldg(brow + f2);
    const float4 w3 = __ldg(weight + f3), b3 = __ldg(brow + f3);

    // Persistent grid-stride over row-strips. Each iter: 4 independent
    // streaming 128-bit loads front-batched (MLP_p1 = 4), stores at the end,
    // so iteration k+1's loads overlap iteration k's store retirement.
    for (unsigned strip = blockIdx.x; strip < N_STRIPS; strip += BLOCKS) {
        const unsigned base = strip * (unsigned)(256u * 4u) + tid;

        float4 x0 = __ldcs(in + base + 0u * 256u);
        float4 x1 = __ldcs(in + base + 1u * 256u);
        float4 x2 = __ldcs(in + base + 2u * 256u);
        float4 x3 = __ldcs(in + base + 3u * 256u);

        float4 r0, r1, r2, r3;
        r0.x = fmaf(x0.x, w0.x, b0.x); r0.y = fmaf(x0.y, w0.y, b0.y);
        r0.z = fmaf(x0.z, w0.z, b0.z); r0.w = fmaf(x0.w, w0.w, b0.w);
        r1.x = fmaf(x1.x, w1.x, b1.x); r1.y = fmaf(x1.y, w1.y, b1.y);
        r1.z = fmaf(x1.z, w1.z, b1.z); r1.w = fmaf(x1.w, w1.w, b1.w);
        r2.x = fmaf(x2.x, w2.x, b2.x); r2.y = fmaf(x2.y, w2.y, b2.y);
        r2.z = fmaf(x2.z, w2.z, b2.z); r2.w = fmaf(x2.w, w2.w, b2.w);
        r3.x = fmaf(x3.x, w3.x, b3.x); r3.y = fmaf(x3.y, w3.y, b3.y);
        r3.z = fmaf(x3.z, w3.z, b3.z); r3.w = fmaf(x3.w, w3.w, b3.w);

        __stcs(out + base + 0u * 256u, r0);
        __stcs(out + base + 1u * 256u, r1);
        __stcs(out + base + 2u * 256u, r2);
        __stcs(out + base + 3u * 256u, r3);
    }
}

extern "C" void kernel_launch(void* const* d_in, const int* in_sizes, int n_in,
                              void* d_out, int out_size)
{
    const float4* in     = (const float4*)d_in[0];   // input  [16384, 4096] f32
    const float4* weight = (const float4*)d_in[1];   // weight [4096]        f32
    const float4* bias   = (const float4*)d_in[2];   // bias   [1000, 4096]  f32
    const int*    nb     = (const int*)   d_in[3];   // nb_distrib scalar int32
    float4*       out    = (float4*)d_out;

    sharelinear_kernel<<<BLOCKS, THREADS>>>(in, weight, bias, nb, out);
}

// round 14
// speedup vs baseline: 1.0512x; 1.0512x over previous
#include <cuda_runtime.h>
#include <cuda_bf16.h>

// out[b,f] = input[b,f] * weight[f] + bias[nb_distrib, f]
// B=16384, F=4096, fp32.
//
// FINAL (R11 best, 81.98us, reproduced twice; resubmitted after infra failure):
//  - Pure HBM-streaming kernel at the mixed read/write ceiling:
//    6408 GB/s = 80.1% of 8 TB/s spec, confirmed identical across two cache
//    policies (default, .cs). Persistent-grid variant regressed (reg pressure
//    58 regs -> occ 47.6% -> fewer in-flight loads).
//  - Exact-cover launch: 16384 blocks x 256 threads x 4 float4 = 2^24, no tail.
//  - Block strip == one row, so weight/bias indices are identical in every
//    block -> those 32KB stay L2-resident; DRAM traffic is the compulsory
//    268MB read + 268MB write only.
//  - 4 independent front-batched LDG.128 per thread (MLP_p1=4); 40 regs,
//    occ 62%, issue 7.6% -- latency fully hidden, DRAM-bound by design.

static constexpr int F_DIM   = 4096;
static constexpr int F_VEC   = F_DIM / 4;              // 1024 float4 per row
static constexpr unsigned TOTAL_VEC = 16384u * F_VEC;  // 2^24 float4

__global__ __launch_bounds__(256)
void sharelinear_kernel(const float4* __restrict__ in,
                        const float4* __restrict__ weight,
                        const float4* __restrict__ bias,
                        const int*    __restrict__ nb_distrib,
                        float4*       __restrict__ out)
{
    const int nb = *nb_distrib;
    const float4* __restrict__ brow = bias + (unsigned)nb * F_VEC;

    const unsigned base = blockIdx.x * (256u * 4u) + threadIdx.x;

    // 4 independent streaming (evict-first) 128-bit loads, front-batched.
    float4 x0 = __ldcs(in + base + 0u * 256u);
    float4 x1 = __ldcs(in + base + 1u * 256u);
    float4 x2 = __ldcs(in + base + 2u * 256u);
    float4 x3 = __ldcs(in + base + 3u * 256u);

    const unsigned f0 = threadIdx.x + 0u * 256u;   // strip is row-aligned
    const unsigned f1 = threadIdx.x + 1u * 256u;
    const unsigned f2 = threadIdx.x + 2u * 256u;
    const unsigned f3 = threadIdx.x + 3u * 256u;

    // Weight/bias: read-only, heavily reused -> NC/default path, L2-resident.
    float4 w0 = __ldg(weight + f0), b0 = __ldg(brow + f0);
    float4 w1 = __ldg(weight + f1), b1 = __ldg(brow + f1);
    float4 w2 = __ldg(weight + f2), b2 = __ldg(brow + f2);
    float4 w3 = __ldg(weight + f3), b3 = __ldg(brow + f3);

    float4 r0, r1, r2, r3;
    r0.x = fmaf(x0.x, w0.x, b0.x); r0.y = fmaf(x0.y, w0.y, b0.y);
    r0.z = fmaf(x0.z, w0.z, b0.z); r0.w = fmaf(x0.w, w0.w, b0.w);
    r1.x = fmaf(x1.x, w1.x, b1.x); r1.y = fmaf(x1.y, w1.y, b1.y);
    r1.z = fmaf(x1.z, w1.z, b1.z); r1.w = fmaf(x1.w, w1.w, b1.w);
    r2.x = fmaf(x2.x, w2.x, b2.x); r2.y = fmaf(x2.y, w2.y, b2.y);
    r2.z = fmaf(x2.z, w2.z, b2.z); r2.w = fmaf(x2.w, w2.w, b2.w);
    r3.x = fmaf(x3.x, w3.x, b3.x); r3.y = fmaf(x3.y, w3.y, b3.y);
    r3.z = fmaf(x3.z, w3.z, b3.z); r3.w = fmaf(x3.w, w3.w, b3.w);

    // Streaming stores: evict-first.
    __stcs(out + base + 0u * 256u, r0);
    __stcs(out + base + 1u * 256u, r1);
    __stcs(out + base + 2u * 256u, r2);
    __stcs(out + base + 3u * 256u, r3);
}

extern "C" void kernel_launch(void* const* d_in, const int* in_sizes, int n_in,
                              void* d_out, int out_size)
{
    const float4* in     = (const float4*)d_in[0];   // input  [16384, 4096] f32
    const float4* weight = (const float4*)d_in[1];   // weight [4096]        f32
    const float4* bias   = (const float4*)d_in[2];   // bias   [1000, 4096]  f32
    const int*    nb     = (const int*)   d_in[3];   // nb_distrib scalar int32
    float4*       out    = (float4*)d_out;

    const int threads = 256;
    const int blocks  = (int)(TOTAL_VEC / (threads * 4));   // 16384, exact cover
    sharelinear_kernel<<<blocks, threads>>>(in, weight, bias, nb, out);
}